// round 8
// baseline (speedup 1.0000x reference)
#include <cuda_runtime.h>

#define BB       8
#define N_SMALL  12288
#define N_FULL   24576
#define CC       256
#define KK       4096
#define SLOTS    8             // max writes tracked per vertex (Poisson(1/6))

// Global scratch (~7.6 MB)
__device__ int g_cnt  [BB * N_FULL];          // writes per vertex
__device__ int g_slots[BB * N_FULL * SLOTS];  // packed (p<<15)|f, unordered
__device__ int g_inv  [BB * N_FULL];          // full-vertex -> image row, or -1
__device__ int g_row  [BB * N_FULL];          // output row -> image row, or -1

// ---------------------------------------------------------------------------
// K1: full-grid init. cnt = 0, inv = -1.
// ---------------------------------------------------------------------------
__global__ void init_kernel()
{
    const int t = blockIdx.x * blockDim.x + threadIdx.x;
    if (t < BB * N_FULL) {
        g_cnt[t] = 0;
        g_inv[t] = -1;
    }
}

// ---------------------------------------------------------------------------
// K2: full-grid fill.
//   Threads [0, B*K): bucket write events. Reference scan at time p = 0..K-1
//   executes vf[T[p]] = vf[F[p]], F[p] = order[b,0,K-1-p], T[p] = order[b,1,K-1-p].
//   Threads [B*K, ...): scatter mask_idx into inv.
// ---------------------------------------------------------------------------
__global__ void fill_kernel(const int* __restrict__ mask_idx,
                            const int* __restrict__ order)
{
    const int t = blockIdx.x * blockDim.x + threadIdx.x;
    if (t < BB * KK) {
        const int b = t / KK;
        const int p = t - b * KK;          // processing time
        const int k = KK - 1 - p;          // order column
        const int f = order[b * 2 * KK + k];
        const int v = order[b * 2 * KK + KK + k];
        const int idx  = b * N_FULL + v;
        const int slot = atomicAdd(&g_cnt[idx], 1);
        if (slot < SLOTS)                   // overflow prob ~5e-8 per run
            __stcs(&g_slots[idx * SLOTS + slot], (p << 15) | f);
    } else {
        const int u = t - BB * KK;
        if (u < BB * N_SMALL) {
            const int b = u / N_SMALL;
            const int i = u - b * N_SMALL;
            g_inv[b * N_FULL + mask_idx[u]] = i;
        }
    }
}

// ---------------------------------------------------------------------------
// K3: one thread per (b, v) — parallel provenance chase.
//   chase(v, P): among writes to v with time < P pick the latest; hop to its
//   source with the new bound; stop when none. Expected hops ~1.2.
// ---------------------------------------------------------------------------
__global__ void chase_kernel()
{
    const int t = blockIdx.x * blockDim.x + threadIdx.x;
    if (t >= BB * N_FULL) return;
    const int b    = t / N_FULL;
    const int base = b * N_FULL;

    int cur = t - base, P = KK;
    for (;;) {
        const int idx = base + cur;
        const int n   = __ldg(&g_cnt[idx]);
        int best = -1;
        for (int j = 0; j < n; j++) {
            int pv = __ldg(&g_slots[idx * SLOTS + j]);
            if ((pv >> 15) < P && pv > best) best = pv;
        }
        if (best < 0) break;
        cur = best & 0x7FFF;
        P   = best >> 15;
    }
    g_row[t] = __ldg(&g_inv[base + cur]);
}

// ---------------------------------------------------------------------------
// K4: row gather with FOUR independent chains per thread.
//   Output split into quarters; thread serves 2 float4 (32B) in each quarter
//   (rows 49152 apart). Four independent index->data chains maximize MLP.
//   A warp covers one contiguous 1 KB row per quarter segment (index is
//   warp-uniform, accesses fully coalesced).
// ---------------------------------------------------------------------------
#define QROWS (BB * N_FULL / 4)              // 49,152 rows per quarter
#define Q4    (QROWS * (CC / 4))             // 3,145,728 float4 per quarter

__global__ void gather_kernel(const float4* __restrict__ img,
                              float4* __restrict__ out)
{
    const int t  = blockIdx.x * blockDim.x + threadIdx.x;
    const int i4 = t * 2;                 // quarter-local first float4 index
    const int rA = i4 >> 6;               // quarter-local row
    const int q  = i4 & 63;               // float4 offset within row

    const int r0 = rA;
    const int r1 = rA + QROWS;
    const int r2 = rA + 2 * QROWS;
    const int r3 = rA + 3 * QROWS;

    // four independent warp-uniform index loads
    const int row0 = __ldg(&g_row[r0]);
    const int row1 = __ldg(&g_row[r1]);
    const int row2 = __ldg(&g_row[r2]);
    const int row3 = __ldg(&g_row[r3]);

    const float4 z = make_float4(0.f, 0.f, 0.f, 0.f);
    float4 a0 = z, a1 = z, b0 = z, b1 = z, c0 = z, c1 = z, d0 = z, d1 = z;

    if (row0 >= 0) {
        const float4* s = img + ((size_t)(r0 / N_FULL) * N_SMALL + row0) * 64 + q;
        a0 = __ldg(s + 0); a1 = __ldg(s + 1);
    }
    if (row1 >= 0) {
        const float4* s = img + ((size_t)(r1 / N_FULL) * N_SMALL + row1) * 64 + q;
        b0 = __ldg(s + 0); b1 = __ldg(s + 1);
    }
    if (row2 >= 0) {
        const float4* s = img + ((size_t)(r2 / N_FULL) * N_SMALL + row2) * 64 + q;
        c0 = __ldg(s + 0); c1 = __ldg(s + 1);
    }
    if (row3 >= 0) {
        const float4* s = img + ((size_t)(r3 / N_FULL) * N_SMALL + row3) * 64 + q;
        d0 = __ldg(s + 0); d1 = __ldg(s + 1);
    }

    __stcs(out + i4 + 0,          a0);
    __stcs(out + i4 + 1,          a1);
    __stcs(out + Q4 + i4 + 0,     b0);
    __stcs(out + Q4 + i4 + 1,     b1);
    __stcs(out + 2 * Q4 + i4 + 0, c0);
    __stcs(out + 2 * Q4 + i4 + 1, c1);
    __stcs(out + 3 * Q4 + i4 + 0, d0);
    __stcs(out + 3 * Q4 + i4 + 1, d1);
}

extern "C" void kernel_launch(void* const* d_in, const int* in_sizes, int n_in,
                              void* d_out, int out_size)
{
    const float* images   = (const float*)d_in[0];
    const int*   mask_idx = (const int*)d_in[1];
    const int*   order    = (const int*)d_in[2];
    float* out = (float*)d_out;

    init_kernel<<<(BB * N_FULL + 255) / 256, 256>>>();

    const int fill_threads = BB * KK + BB * N_SMALL;   // 131072
    fill_kernel<<<(fill_threads + 255) / 256, 256>>>(mask_idx, order);

    chase_kernel<<<(BB * N_FULL + 255) / 256, 256>>>();

    const int nthreads = Q4 / 2;           // 1,572,864 threads
    gather_kernel<<<nthreads / 256, 256>>>((const float4*)images, (float4*)out);
}

// round 9
// speedup vs baseline: 1.1041x; 1.1041x over previous
#include <cuda_runtime.h>

#define BB       8
#define N_SMALL  12288
#define N_FULL   24576
#define CC       256
#define KK       4096
#define SLOTS    8             // max writes tracked per vertex (Poisson(1/6))

// Global scratch (~7.6 MB). Zero-initialized at module load == empty state:
//   g_cnt == 0  : no write events bucketed
//   g_inv == 0  : "vertex not in mask" (we store image_row + 1, 0 = absent)
// The LAST kernel (gather) restores this empty state for the next replay.
__device__ int g_cnt  [BB * N_FULL];          // writes per vertex
__device__ int g_slots[BB * N_FULL * SLOTS];  // packed (p<<15)|f, unordered
__device__ int g_inv  [BB * N_FULL];          // full-vertex -> image row + 1, 0 = none
__device__ int g_row  [BB * N_FULL];          // output row -> image row, or -1

// ---------------------------------------------------------------------------
// K1: full-grid fill.
//   Threads [0, B*K): bucket write events. Reference scan at time p = 0..K-1
//   executes vf[T[p]] = vf[F[p]], F[p] = order[b,0,K-1-p], T[p] = order[b,1,K-1-p].
//   Threads [B*K, ...): scatter mask_idx into inv (value = image row + 1).
// ---------------------------------------------------------------------------
__global__ void fill_kernel(const int* __restrict__ mask_idx,
                            const int* __restrict__ order)
{
    const int t = blockIdx.x * blockDim.x + threadIdx.x;
    if (t < BB * KK) {
        const int b = t / KK;
        const int p = t - b * KK;          // processing time
        const int k = KK - 1 - p;          // order column
        const int f = order[b * 2 * KK + k];
        const int v = order[b * 2 * KK + KK + k];
        const int idx  = b * N_FULL + v;
        const int slot = atomicAdd(&g_cnt[idx], 1);
        if (slot < SLOTS)                   // overflow prob ~5e-8 per run
            __stcs(&g_slots[idx * SLOTS + slot], (p << 15) | f);
    } else {
        const int u = t - BB * KK;
        if (u < BB * N_SMALL) {
            const int b = u / N_SMALL;
            const int i = u - b * N_SMALL;
            g_inv[b * N_FULL + mask_idx[u]] = i + 1;
        }
    }
}

// ---------------------------------------------------------------------------
// K2: one thread per (b, v) — parallel provenance chase.
//   chase(v, P): among writes to v with time < P pick the latest; hop to its
//   source with the new bound; stop when none. Expected hops ~1.2.
// ---------------------------------------------------------------------------
__global__ void chase_kernel()
{
    const int t = blockIdx.x * blockDim.x + threadIdx.x;
    if (t >= BB * N_FULL) return;
    const int b    = t / N_FULL;
    const int base = b * N_FULL;

    int cur = t - base, P = KK;
    for (;;) {
        const int idx = base + cur;
        const int n   = __ldg(&g_cnt[idx]);
        int best = -1;
        for (int j = 0; j < n; j++) {
            int pv = __ldg(&g_slots[idx * SLOTS + j]);
            if ((pv >> 15) < P && pv > best) best = pv;
        }
        if (best < 0) break;
        cur = best & 0x7FFF;
        P   = best >> 15;
    }
    g_row[t] = __ldg(&g_inv[base + cur]) - 1;   // -1 = zero row
}

// ---------------------------------------------------------------------------
// K3: row gather with TWO independent chains per thread (R7 proven form).
//   Thread t serves 2 float4 (32B) in the FIRST half of the output and
//   2 float4 in the SECOND half. Two independent index->data chains.
//   A warp covers one contiguous 1 KB row per segment (warp-uniform index,
//   fully coalesced). ALSO restores g_cnt/g_inv empty state for next replay.
// ---------------------------------------------------------------------------
#define HALF4 (BB * N_FULL * (CC / 4) / 2)   // 6,291,456 float4 per half

__global__ void gather_kernel(const float4* __restrict__ img,
                              float4* __restrict__ out)
{
    const int t    = blockIdx.x * blockDim.x + threadIdx.x;

    // restore empty scratch state for the next graph replay (no reads race:
    // this kernel only reads g_row)
    if (t < BB * N_FULL) {
        __stcs(&g_cnt[t], 0);
        __stcs(&g_inv[t], 0);
    }

    const int i4   = t * 2;               // first float4 index (half-local)
    const int rA   = i4 >> 6;             // row in first half
    const int q    = i4 & 63;             // float4 offset within row
    const int rB   = rA + (BB * N_FULL / 2);

    // independent index loads (both warp-uniform broadcasts)
    const int rowA = __ldg(&g_row[rA]);
    const int rowB = __ldg(&g_row[rB]);

    const int bA = rA / N_FULL;
    const int bB = rB / N_FULL;

    float4 a0, a1, b0, b1;
    const float4 z = make_float4(0.f, 0.f, 0.f, 0.f);

    if (rowA >= 0) {
        const float4* s = img + ((size_t)bA * N_SMALL + rowA) * 64 + q;
        a0 = __ldg(s + 0);
        a1 = __ldg(s + 1);
    } else { a0 = a1 = z; }

    if (rowB >= 0) {
        const float4* s = img + ((size_t)bB * N_SMALL + rowB) * 64 + q;
        b0 = __ldg(s + 0);
        b1 = __ldg(s + 1);
    } else { b0 = b1 = z; }

    __stcs(out + i4 + 0, a0);
    __stcs(out + i4 + 1, a1);
    __stcs(out + HALF4 + i4 + 0, b0);
    __stcs(out + HALF4 + i4 + 1, b1);
}

extern "C" void kernel_launch(void* const* d_in, const int* in_sizes, int n_in,
                              void* d_out, int out_size)
{
    const float* images   = (const float*)d_in[0];
    const int*   mask_idx = (const int*)d_in[1];
    const int*   order    = (const int*)d_in[2];
    float* out = (float*)d_out;

    const int fill_threads = BB * KK + BB * N_SMALL;   // 131072
    fill_kernel<<<(fill_threads + 255) / 256, 256>>>(mask_idx, order);

    chase_kernel<<<(BB * N_FULL + 255) / 256, 256>>>();

    const int nthreads = HALF4 / 2;        // 3,145,728 threads
    gather_kernel<<<nthreads / 256, 256>>>((const float4*)images, (float4*)out);
}